// round 8
// baseline (speedup 1.0000x reference)
#include <cuda_runtime.h>
#include <cstdint>

#define T_TOK    16384
#define DIM      2048
#define NEXP     64
#define NB       4
#define SEQ      4096
#define BM       32              // tokens per CTA
#define BK       32              // k per chunk
#define NCHUNK   (DIM / BK)      // 64
#define NTHREADS 256
#define GRID     (T_TOK / BM)    // 512

// smem: two stages, each A2[32][34] float2 + B2[64][34] float2
#define A_K2     34
#define B_K2     34
#define A2_BYTES (BM * A_K2 * 8)          // 8704
#define B2_BYTES (NEXP * B_K2 * 8)        // 17408
#define STAGE_B  (A2_BYTES + B2_BYTES)    // 26112
#define SMEM_BYTES (2 * STAGE_B)          // 52224
// epilogue reuse: red[4][32][68] f32 (34816 B) + sc[32][68] f32 (8704 B) = 43520 <= 52224

__device__ float        g_score_sum[NB * NEXP];   // zero-init; last block resets
__device__ unsigned int g_counts[NB * NEXP];
__device__ unsigned int g_done;

__device__ __forceinline__ float2 split2(float x) {
    uint32_t h;
    asm("cvt.rna.tf32.f32 %0, %1;" : "=r"(h) : "f"(x));
    float hf = __uint_as_float(h);
    float r = x - hf;
    uint32_t l;
    asm("cvt.rna.tf32.f32 %0, %1;" : "=r"(l) : "f"(r));
    return make_float2(hf, __uint_as_float(l));
}

__device__ __forceinline__ void mma_tf32(float* c,
                                         float a0, float a1, float a2, float a3,
                                         float b0, float b1) {
    asm volatile(
        "mma.sync.aligned.m16n8k8.row.col.f32.tf32.tf32.f32 "
        "{%0,%1,%2,%3}, {%4,%5,%6,%7}, {%8,%9}, {%0,%1,%2,%3};"
        : "+f"(c[0]), "+f"(c[1]), "+f"(c[2]), "+f"(c[3])
        : "r"(__float_as_uint(a0)), "r"(__float_as_uint(a1)),
          "r"(__float_as_uint(a2)), "r"(__float_as_uint(a3)),
          "r"(__float_as_uint(b0)), "r"(__float_as_uint(b1)));
}

__global__ __launch_bounds__(NTHREADS, 2)
void moe_gate_mma(const float* __restrict__ X,
                  const float* __restrict__ W,
                  float* __restrict__ out)
{
    extern __shared__ char smem[];
    __shared__ unsigned int cnt[NEXP];
    __shared__ int last_flag;

    const int tid  = threadIdx.x;
    const int wid  = tid >> 5;
    const int lane = tid & 31;
    const int g    = lane >> 2;       // 0..7
    const int tg   = lane & 3;        // 0..3
    const int tgp  = wid >> 2;        // token group 0..1 (16 tokens each)
    const int ks   = wid & 3;         // k-slice 0..3 (k8 each)
    const int kb   = ks * 8;
    const int tok0 = blockIdx.x * BM;

    // loader geometry: X: 1 float4/thread/chunk; W: 2 float4/thread/chunk
    const int xrow = tid >> 3;        // 0..31
    const int xc4  = tid & 7;         // 0..7

    float acc_h[8][4], acc_l[8][4];
#pragma unroll
    for (int nt = 0; nt < 8; nt++)
#pragma unroll
        for (int i = 0; i < 4; i++) { acc_h[nt][i] = 0.0f; acc_l[nt][i] = 0.0f; }

    float4 ra, rw0, rw1;

    // ---- prolog: load + stage chunk 0 ----
    ra  = *(const float4*)&X[(size_t)(tok0 + xrow) * DIM + xc4 * 4];
    rw0 = *(const float4*)&W[(size_t)(xrow)      * DIM + xc4 * 4];
    rw1 = *(const float4*)&W[(size_t)(xrow + 32) * DIM + xc4 * 4];
    {
        float2* A2 = (float2*)(smem);
        float2* B2 = (float2*)(smem + A2_BYTES);
        float av[4] = { ra.x, ra.y, ra.z, ra.w };
        float w0[4] = { rw0.x, rw0.y, rw0.z, rw0.w };
        float w1[4] = { rw1.x, rw1.y, rw1.z, rw1.w };
#pragma unroll
        for (int j = 0; j < 4; j++) {
            A2[xrow * A_K2 + xc4 * 4 + j]        = split2(av[j]);
            B2[xrow * B_K2 + xc4 * 4 + j]        = split2(w0[j]);
            B2[(xrow + 32) * B_K2 + xc4 * 4 + j] = split2(w1[j]);
        }
    }
    __syncthreads();

    for (int kt = 0; kt < NCHUNK; kt++) {
        const int stage = kt & 1;

        // ---- prefetch next chunk into regs ----
        if (kt + 1 < NCHUNK) {
            const int k0 = (kt + 1) * BK;
            ra  = *(const float4*)&X[(size_t)(tok0 + xrow) * DIM + k0 + xc4 * 4];
            rw0 = *(const float4*)&W[(size_t)(xrow)      * DIM + k0 + xc4 * 4];
            rw1 = *(const float4*)&W[(size_t)(xrow + 32) * DIM + k0 + xc4 * 4];
        }

        // ---- compute this warp's k8 slice of the chunk ----
        {
            const float2* A2 = (const float2*)(smem + stage * STAGE_B);
            const float2* B2 = (const float2*)(smem + stage * STAGE_B + A2_BYTES);
            const int t0 = tgp * 16 + g;
            float2 a0 = A2[t0 * A_K2 + kb + tg];
            float2 a1 = A2[(t0 + 8) * A_K2 + kb + tg];
            float2 a2 = A2[t0 * A_K2 + kb + tg + 4];
            float2 a3 = A2[(t0 + 8) * A_K2 + kb + tg + 4];
#pragma unroll
            for (int nt = 0; nt < 8; nt++) {
                const int e = nt * 8 + g;
                float2 b0 = B2[e * B_K2 + kb + tg];
                float2 b1 = B2[e * B_K2 + kb + tg + 4];
                mma_tf32(acc_h[nt], a0.x, a1.x, a2.x, a3.x, b0.x, b1.x);
                mma_tf32(acc_l[nt], a0.x, a1.x, a2.x, a3.x, b0.y, b1.y);
                mma_tf32(acc_l[nt], a0.y, a1.y, a2.y, a3.y, b0.x, b1.x);
                mma_tf32(acc_l[nt], a0.y, a1.y, a2.y, a3.y, b0.y, b1.y);
            }
        }

        // ---- stage prefetched regs into other buffer ----
        if (kt + 1 < NCHUNK) {
            float2* A2 = (float2*)(smem + (stage ^ 1) * STAGE_B);
            float2* B2 = (float2*)(smem + (stage ^ 1) * STAGE_B + A2_BYTES);
            float av[4] = { ra.x, ra.y, ra.z, ra.w };
            float w0[4] = { rw0.x, rw0.y, rw0.z, rw0.w };
            float w1[4] = { rw1.x, rw1.y, rw1.z, rw1.w };
#pragma unroll
            for (int j = 0; j < 4; j++) {
                A2[xrow * A_K2 + xc4 * 4 + j]        = split2(av[j]);
                B2[xrow * B_K2 + xc4 * 4 + j]        = split2(w0[j]);
                B2[(xrow + 32) * B_K2 + xc4 * 4 + j] = split2(w1[j]);
            }
        }
        __syncthreads();
    }

    // ---- cross-slice reduction ----
    float* red = (float*)smem;                         // [4][32][68]
    float* sc  = (float*)(smem + 4 * 32 * 68 * 4);     // [32][68]
    {
        const int t0 = tgp * 16 + g;
#pragma unroll
        for (int nt = 0; nt < 8; nt++) {
            const int e = nt * 8 + 2 * tg;
            *(float2*)&red[(ks * 32 + t0) * 68 + e] =
                make_float2(acc_h[nt][0] + acc_l[nt][0], acc_h[nt][1] + acc_l[nt][1]);
            *(float2*)&red[(ks * 32 + t0 + 8) * 68 + e] =
                make_float2(acc_h[nt][2] + acc_l[nt][2], acc_h[nt][3] + acc_l[nt][3]);
        }
    }
    if (tid < NEXP) cnt[tid] = 0u;
    __syncthreads();

    for (int i = tid; i < BM * NEXP; i += NTHREADS) {
        const int t = i >> 6, e = i & 63;
        sc[t * 68 + e] = red[t * 68 + e]
                       + red[(32 * 68) + t * 68 + e]
                       + red[2 * (32 * 68) + t * 68 + e]
                       + red[3 * (32 * 68) + t * 68 + e];
    }
    __syncthreads();

    // ---- per-token softmax + top-2 ----
    if (tid < BM) {
        float v[64];
#pragma unroll
        for (int e = 0; e < NEXP; e++) v[e] = sc[tid * 68 + e];
        float mx = v[0];
#pragma unroll
        for (int e = 1; e < NEXP; e++) mx = fmaxf(mx, v[e]);
        float sum = 0.0f;
#pragma unroll
        for (int e = 0; e < NEXP; e++) { v[e] = expf(v[e] - mx); sum += v[e]; }
        float inv = 1.0f / sum;

        float v1 = -1.0f, v2 = -1.0f;
        int i1 = 0, i2 = 0;
#pragma unroll
        for (int e = 0; e < NEXP; e++) {
            float p = v[e] * inv;
            sc[tid * 68 + e] = p;
            if (p > v1) { v2 = v1; i2 = i1; v1 = p; i1 = e; }
            else if (p > v2) { v2 = p; i2 = e; }
        }
        float tot = v1 + v2 + 1e-20f;
        const int gt = tok0 + tid;
        out[2 * gt + 0] = (float)i1;
        out[2 * gt + 1] = (float)i2;
        out[2 * T_TOK + 2 * gt + 0] = v1 / tot;
        out[2 * T_TOK + 2 * gt + 1] = v2 / tot;

        atomicAdd(&cnt[i1], 1u);
        atomicAdd(&cnt[i2], 1u);
    }
    __syncthreads();

    // ---- per-expert sums -> global ----
    if (tid < NEXP) {
        float cs = 0.0f;
#pragma unroll
        for (int t = 0; t < BM; t++) cs += sc[t * 68 + tid];
        const int b = tok0 / SEQ;
        atomicAdd(&g_score_sum[b * NEXP + tid], cs);
        atomicAdd(&g_counts[b * NEXP + tid], cnt[tid]);
    }

    // ---- last-block finalize (aux loss) ----
    __threadfence();
    __syncthreads();
    if (tid == 0) {
        unsigned int v = atomicAdd(&g_done, 1u);
        last_flag = (v == (unsigned int)(GRID - 1));
    }
    __syncthreads();
    if (last_flag) {
        float* redf = (float*)smem;   // 256 floats
        const int i = tid;            // 256 = NB*NEXP
        float sv = *((volatile float*)&g_score_sum[i]);
        unsigned int cv = *((volatile unsigned int*)&g_counts[i]);
        float v = (float)cv * ((float)NEXP / (float)(SEQ * 2)) * (sv / (float)SEQ);
        g_score_sum[i] = 0.0f;
        g_counts[i] = 0u;
        if (tid == 0) g_done = 0u;
        redf[i] = v;
        __syncthreads();
        for (int s = (NB * NEXP) / 2; s > 0; s >>= 1) {
            if (i < s) redf[i] += redf[i + s];
            __syncthreads();
        }
        if (i == 0) out[4 * T_TOK] = redf[0] * (0.1f / (float)NB);
    }
}

extern "C" void kernel_launch(void* const* d_in, const int* in_sizes, int n_in,
                              void* d_out, int out_size) {
    const float* X = (const float*)d_in[0];   // [4,4096,2048] f32
    const float* W = (const float*)d_in[1];   // [64,2048] f32
    float* out = (float*)d_out;

    cudaFuncSetAttribute(moe_gate_mma, cudaFuncAttributeMaxDynamicSharedMemorySize, SMEM_BYTES);
    moe_gate_mma<<<GRID, NTHREADS, SMEM_BYTES>>>(X, W, out);
}

// round 9
// speedup vs baseline: 1.0447x; 1.0447x over previous
#include <cuda_runtime.h>
#include <cstdint>

#define T_TOK    16384
#define DIM      2048
#define NEXP     64
#define NB       4
#define SEQ      4096
#define BM       64              // tokens per CTA
#define BK       32              // k per chunk
#define NCHUNK   (DIM / BK)      // 64
#define NTHREADS 256
#define GRID     (T_TOK / BM)    // 256

// smem: two stages, each A2[64][34] float2 + B2[64][34] float2
#define AB_K2    34
#define A2_BYTES (BM * AB_K2 * 8)         // 17408
#define B2_BYTES (NEXP * AB_K2 * 8)       // 17408
#define STAGE_B  (A2_BYTES + B2_BYTES)    // 34816
#define SMEM_BYTES (2 * STAGE_B)          // 69632
// epilogue reuse: red[4][64][68] f32 = 69632 B (exactly fits)

__device__ float        g_score_sum[NB * NEXP];   // zero-init; last block resets
__device__ unsigned int g_counts[NB * NEXP];
__device__ unsigned int g_done;

__device__ __forceinline__ float2 split2(float x) {
    uint32_t h;
    asm("cvt.rna.tf32.f32 %0, %1;" : "=r"(h) : "f"(x));
    float hf = __uint_as_float(h);
    float r = x - hf;
    uint32_t l;
    asm("cvt.rna.tf32.f32 %0, %1;" : "=r"(l) : "f"(r));
    return make_float2(hf, __uint_as_float(l));
}

__device__ __forceinline__ void mma_tf32(float* c,
                                         float a0, float a1, float a2, float a3,
                                         float b0, float b1) {
    asm volatile(
        "mma.sync.aligned.m16n8k8.row.col.f32.tf32.tf32.f32 "
        "{%0,%1,%2,%3}, {%4,%5,%6,%7}, {%8,%9}, {%0,%1,%2,%3};"
        : "+f"(c[0]), "+f"(c[1]), "+f"(c[2]), "+f"(c[3])
        : "r"(__float_as_uint(a0)), "r"(__float_as_uint(a1)),
          "r"(__float_as_uint(a2)), "r"(__float_as_uint(a3)),
          "r"(__float_as_uint(b0)), "r"(__float_as_uint(b1)));
}

__global__ __launch_bounds__(NTHREADS, 2)
void moe_gate_mma(const float* __restrict__ X,
                  const float* __restrict__ W,
                  float* __restrict__ out)
{
    extern __shared__ char smem[];
    __shared__ unsigned int cnt[NEXP];
    __shared__ int last_flag;

    const int tid  = threadIdx.x;
    const int wid  = tid >> 5;
    const int lane = tid & 31;
    const int g    = lane >> 2;       // 0..7
    const int tg   = lane & 3;        // 0..3
    const int tgp  = wid >> 2;        // token group 0..1 (32 tokens each)
    const int ks   = wid & 3;         // k-slice 0..3 (k8 each)
    const int kb   = ks * 8;
    const int tok0 = blockIdx.x * BM;

    // loader geometry: idx = tid, tid+256 -> row = idx>>3 (0..63), c4 = idx&7
    const int lr0 = tid >> 3;         // 0..31
    const int lr1 = lr0 + 32;         // 32..63
    const int lc4 = tid & 7;          // 0..7

    // stage pointers (float2 units)
    float2* A2p[2] = { (float2*)smem, (float2*)(smem + STAGE_B) };
    float2* B2p[2] = { (float2*)(smem + A2_BYTES), (float2*)(smem + STAGE_B + A2_BYTES) };

    // fragment offsets (float2 units)
    const int offA0 = (tgp * 32 + g) * AB_K2 + kb + tg;   // mf0, row g
    const int offB0 = g * AB_K2 + kb + tg;                // nt 0

    float acc[2][8][4];
#pragma unroll
    for (int mf = 0; mf < 2; mf++)
#pragma unroll
        for (int nt = 0; nt < 8; nt++)
#pragma unroll
            for (int i = 0; i < 4; i++) acc[mf][nt][i] = 0.0f;

    const float* Xp0 = X + (size_t)(tok0 + lr0) * DIM + lc4 * 4;
    const float* Xp1 = X + (size_t)(tok0 + lr1) * DIM + lc4 * 4;
    const float* Wp0 = W + (size_t)lr0 * DIM + lc4 * 4;
    const float* Wp1 = W + (size_t)lr1 * DIM + lc4 * 4;

    float4 ra0, ra1, rw0, rw1;

    // ---- prolog: load + stage chunk 0 ----
    ra0 = *(const float4*)Xp0;  ra1 = *(const float4*)Xp1;
    rw0 = *(const float4*)Wp0;  rw1 = *(const float4*)Wp1;
    {
        float2* A2 = A2p[0];
        float2* B2 = B2p[0];
        // each float4 -> 2x float4 STS (pairs of split2)
        float2 s0, s1;
        s0 = split2(ra0.x); s1 = split2(ra0.y);
        *(float4*)&A2[lr0 * AB_K2 + lc4 * 4]     = make_float4(s0.x, s0.y, s1.x, s1.y);
        s0 = split2(ra0.z); s1 = split2(ra0.w);
        *(float4*)&A2[lr0 * AB_K2 + lc4 * 4 + 2] = make_float4(s0.x, s0.y, s1.x, s1.y);
        s0 = split2(ra1.x); s1 = split2(ra1.y);
        *(float4*)&A2[lr1 * AB_K2 + lc4 * 4]     = make_float4(s0.x, s0.y, s1.x, s1.y);
        s0 = split2(ra1.z); s1 = split2(ra1.w);
        *(float4*)&A2[lr1 * AB_K2 + lc4 * 4 + 2] = make_float4(s0.x, s0.y, s1.x, s1.y);
        s0 = split2(rw0.x); s1 = split2(rw0.y);
        *(float4*)&B2[lr0 * AB_K2 + lc4 * 4]     = make_float4(s0.x, s0.y, s1.x, s1.y);
        s0 = split2(rw0.z); s1 = split2(rw0.w);
        *(float4*)&B2[lr0 * AB_K2 + lc4 * 4 + 2] = make_float4(s0.x, s0.y, s1.x, s1.y);
        s0 = split2(rw1.x); s1 = split2(rw1.y);
        *(float4*)&B2[lr1 * AB_K2 + lc4 * 4]     = make_float4(s0.x, s0.y, s1.x, s1.y);
        s0 = split2(rw1.z); s1 = split2(rw1.w);
        *(float4*)&B2[lr1 * AB_K2 + lc4 * 4 + 2] = make_float4(s0.x, s0.y, s1.x, s1.y);
    }
    __syncthreads();

    for (int kt = 0; kt < NCHUNK; kt++) {
        const int stage = kt & 1;

        // ---- prefetch next chunk into regs ----
        if (kt + 1 < NCHUNK) {
            Xp0 += BK; Xp1 += BK; Wp0 += BK; Wp1 += BK;
            ra0 = *(const float4*)Xp0;  ra1 = *(const float4*)Xp1;
            rw0 = *(const float4*)Wp0;  rw1 = *(const float4*)Wp1;
        }

        // ---- compute this warp's m32 x n64 x k8 slice ----
        {
            const float2* A2 = A2p[stage];
            const float2* B2 = B2p[stage];
            float2 a[2][4];
#pragma unroll
            for (int mf = 0; mf < 2; mf++) {
                const int base = offA0 + mf * 16 * AB_K2;
                a[mf][0] = A2[base];
                a[mf][1] = A2[base + 8 * AB_K2];
                a[mf][2] = A2[base + 4];
                a[mf][3] = A2[base + 8 * AB_K2 + 4];
            }
#pragma unroll
            for (int nt = 0; nt < 8; nt++) {
                const int be = offB0 + nt * 8 * AB_K2;
                float2 b0 = B2[be];
                float2 b1 = B2[be + 4];
#pragma unroll
                for (int mf = 0; mf < 2; mf++) {
                    mma_tf32(acc[mf][nt], a[mf][0].x, a[mf][1].x, a[mf][2].x, a[mf][3].x, b0.x, b1.x);
                    mma_tf32(acc[mf][nt], a[mf][0].x, a[mf][1].x, a[mf][2].x, a[mf][3].x, b0.y, b1.y);
                    mma_tf32(acc[mf][nt], a[mf][0].y, a[mf][1].y, a[mf][2].y, a[mf][3].y, b0.x, b1.x);
                    mma_tf32(acc[mf][nt], a[mf][0].y, a[mf][1].y, a[mf][2].y, a[mf][3].y, b0.y, b1.y);
                }
            }
        }

        // ---- stage prefetched regs into other buffer ----
        if (kt + 1 < NCHUNK) {
            float2* A2 = A2p[stage ^ 1];
            float2* B2 = B2p[stage ^ 1];
            float2 s0, s1;
            s0 = split2(ra0.x); s1 = split2(ra0.y);
            *(float4*)&A2[lr0 * AB_K2 + lc4 * 4]     = make_float4(s0.x, s0.y, s1.x, s1.y);
            s0 = split2(ra0.z); s1 = split2(ra0.w);
            *(float4*)&A2[lr0 * AB_K2 + lc4 * 4 + 2] = make_float4(s0.x, s0.y, s1.x, s1.y);
            s0 = split2(ra1.x); s1 = split2(ra1.y);
            *(float4*)&A2[lr1 * AB_K2 + lc4 * 4]     = make_float4(s0.x, s0.y, s1.x, s1.y);
            s0 = split2(ra1.z); s1 = split2(ra1.w);
            *(float4*)&A2[lr1 * AB_K2 + lc4 * 4 + 2] = make_float4(s0.x, s0.y, s1.x, s1.y);
            s0 = split2(rw0.x); s1 = split2(rw0.y);
            *(float4*)&B2[lr0 * AB_K2 + lc4 * 4]     = make_float4(s0.x, s0.y, s1.x, s1.y);
            s0 = split2(rw0.z); s1 = split2(rw0.w);
            *(float4*)&B2[lr0 * AB_K2 + lc4 * 4 + 2] = make_float4(s0.x, s0.y, s1.x, s1.y);
            s0 = split2(rw1.x); s1 = split2(rw1.y);
            *(float4*)&B2[lr1 * AB_K2 + lc4 * 4]     = make_float4(s0.x, s0.y, s1.x, s1.y);
            s0 = split2(rw1.z); s1 = split2(rw1.w);
            *(float4*)&B2[lr1 * AB_K2 + lc4 * 4 + 2] = make_float4(s0.x, s0.y, s1.x, s1.y);
        }
        __syncthreads();
    }

    // ---- cross-slice reduction: red[4][64][68] ----
    float* red = (float*)smem;
    {
#pragma unroll
        for (int mf = 0; mf < 2; mf++) {
            const int row = tgp * 32 + mf * 16 + g;
#pragma unroll
            for (int nt = 0; nt < 8; nt++) {
                const int e = nt * 8 + 2 * tg;
                *(float2*)&red[((ks * BM) + row) * 68 + e] =
                    make_float2(acc[mf][nt][0], acc[mf][nt][1]);
                *(float2*)&red[((ks * BM) + row + 8) * 68 + e] =
                    make_float2(acc[mf][nt][2], acc[mf][nt][3]);
            }
        }
    }
    if (tid < NEXP) cnt[tid] = 0u;
    __syncthreads();

    // reduce 4 slices into slice 0 (sc = red)
    for (int i = tid; i < BM * NEXP; i += NTHREADS) {
        const int t = i >> 6, e = i & 63;
        float s = red[t * 68 + e]
                + red[(BM * 68) + t * 68 + e]
                + red[2 * (BM * 68) + t * 68 + e]
                + red[3 * (BM * 68) + t * 68 + e];
        red[t * 68 + e] = s;
    }
    __syncthreads();

    float* sc = red;   // [64][68]

    // ---- per-token softmax + top-2 ----
    if (tid < BM) {
        float v[64];
#pragma unroll
        for (int e = 0; e < NEXP; e++) v[e] = sc[tid * 68 + e];
        float mx = v[0];
#pragma unroll
        for (int e = 1; e < NEXP; e++) mx = fmaxf(mx, v[e]);
        float sum = 0.0f;
#pragma unroll
        for (int e = 0; e < NEXP; e++) { v[e] = expf(v[e] - mx); sum += v[e]; }
        float inv = 1.0f / sum;

        float v1 = -1.0f, v2 = -1.0f;
        int i1 = 0, i2 = 0;
#pragma unroll
        for (int e = 0; e < NEXP; e++) {
            float p = v[e] * inv;
            sc[tid * 68 + e] = p;
            if (p > v1) { v2 = v1; i2 = i1; v1 = p; i1 = e; }
            else if (p > v2) { v2 = p; i2 = e; }
        }
        float tot = v1 + v2 + 1e-20f;
        const int gt = tok0 + tid;
        out[2 * gt + 0] = (float)i1;
        out[2 * gt + 1] = (float)i2;
        out[2 * T_TOK + 2 * gt + 0] = v1 / tot;
        out[2 * T_TOK + 2 * gt + 1] = v2 / tot;

        atomicAdd(&cnt[i1], 1u);
        atomicAdd(&cnt[i2], 1u);
    }
    __syncthreads();

    // ---- per-expert sums -> global ----
    if (tid < NEXP) {
        float cs = 0.0f;
#pragma unroll 8
        for (int t = 0; t < BM; t++) cs += sc[t * 68 + tid];
        const int b = tok0 / SEQ;
        atomicAdd(&g_score_sum[b * NEXP + tid], cs);
        atomicAdd(&g_counts[b * NEXP + tid], cnt[tid]);
    }

    // ---- last-block finalize (aux loss) ----
    __threadfence();
    __syncthreads();
    if (tid == 0) {
        unsigned int v = atomicAdd(&g_done, 1u);
        last_flag = (v == (unsigned int)(GRID - 1));
    }
    __syncthreads();
    if (last_flag) {
        float* redf = (float*)smem;   // 256 floats
        const int i = tid;            // 256 = NB*NEXP
        float sv = *((volatile float*)&g_score_sum[i]);
        unsigned int cv = *((volatile unsigned int*)&g_counts[i]);
        float v = (float)cv * ((float)NEXP / (float)(SEQ * 2)) * (sv / (float)SEQ);
        g_score_sum[i] = 0.0f;
        g_counts[i] = 0u;
        if (tid == 0) g_done = 0u;
        redf[i] = v;
        __syncthreads();
        for (int s = (NB * NEXP) / 2; s > 0; s >>= 1) {
            if (i < s) redf[i] += redf[i + s];
            __syncthreads();
        }
        if (i == 0) out[4 * T_TOK] = redf[0] * (0.1f / (float)NB);
    }
}

extern "C" void kernel_launch(void* const* d_in, const int* in_sizes, int n_in,
                              void* d_out, int out_size) {
    const float* X = (const float*)d_in[0];   // [4,4096,2048] f32
    const float* W = (const float*)d_in[1];   // [64,2048] f32
    float* out = (float*)d_out;

    cudaFuncSetAttribute(moe_gate_mma, cudaFuncAttributeMaxDynamicSharedMemorySize, SMEM_BYTES);
    moe_gate_mma<<<GRID, NTHREADS, SMEM_BYTES>>>(X, W, out);
}

// round 10
// speedup vs baseline: 1.2147x; 1.1627x over previous
#include <cuda_runtime.h>
#include <cstdint>

#define T_TOK    16384
#define DIM      2048
#define NEXP     64
#define NB       4
#define SEQ      4096
#define BM       64              // tokens per CTA
#define BK       32              // k per chunk
#define NCHUNK   (DIM / BK)      // 64
#define NTHREADS 256
#define GRID     (T_TOK / BM)    // 256

// smem: two stages; each stage = A4[64*17] float4 + B4[64*17] float4
// float4 at [row][s][tg] = idx row*17 + s*4 + tg  (pad: 17 float4 per row)
#define ROW4     17
#define A4_CNT   (BM * ROW4)              // 1088 float4
#define A4_BYTES (A4_CNT * 16)            // 17408
#define B4_BYTES (A4_BYTES)               // 17408
#define STAGE_B  (A4_BYTES + B4_BYTES)    // 34816
#define SMEM_BYTES (2 * STAGE_B)          // 69632
// epilogue reuse: red[4][64][68] f32 = 69632 B (exact fit)

__device__ float        g_score_sum[NB * NEXP];
__device__ unsigned int g_counts[NB * NEXP];
__device__ unsigned int g_done;

__device__ __forceinline__ float2 split2(float x) {
    uint32_t h;
    asm("cvt.rna.tf32.f32 %0, %1;" : "=r"(h) : "f"(x));
    float hf = __uint_as_float(h);
    float r = x - hf;
    uint32_t l;
    asm("cvt.rna.tf32.f32 %0, %1;" : "=r"(l) : "f"(r));
    return make_float2(hf, __uint_as_float(l));
}

__device__ __forceinline__ void mma_tf32(float* c,
                                         float a0, float a1, float a2, float a3,
                                         float b0, float b1) {
    asm volatile(
        "mma.sync.aligned.m16n8k8.row.col.f32.tf32.tf32.f32 "
        "{%0,%1,%2,%3}, {%4,%5,%6,%7}, {%8,%9}, {%0,%1,%2,%3};"
        : "+f"(c[0]), "+f"(c[1]), "+f"(c[2]), "+f"(c[3])
        : "r"(__float_as_uint(a0)), "r"(__float_as_uint(a1)),
          "r"(__float_as_uint(a2)), "r"(__float_as_uint(a3)),
          "r"(__float_as_uint(b0)), "r"(__float_as_uint(b1)));
}

__device__ __forceinline__ void stage_pack(float4* dst4, int arow, int as,
                                           float4 f0, float4 f1) {
    float xv[8] = { f0.x, f0.y, f0.z, f0.w, f1.x, f1.y, f1.z, f1.w };
    float2 s[8];
#pragma unroll
    for (int j = 0; j < 8; j++) s[j] = split2(xv[j]);
    const int base = arow * ROW4 + as * 4;
#pragma unroll
    for (int t = 0; t < 4; t++)
        dst4[base + t] = make_float4(s[t].x, s[t].y, s[t + 4].x, s[t + 4].y);
}

__global__ __launch_bounds__(NTHREADS, 2)
void moe_gate_mma(const float* __restrict__ X,
                  const float* __restrict__ W,
                  float* __restrict__ out)
{
    extern __shared__ char smem[];
    __shared__ unsigned int cnt[NEXP];
    __shared__ int last_flag;

    const int tid  = threadIdx.x;
    const int wid  = tid >> 5;
    const int lane = tid & 31;
    const int g    = lane >> 2;       // 0..7
    const int tg   = lane & 3;        // 0..3
    const int tgp  = wid >> 2;        // token group 0..1 (32 tokens each)
    const int ks   = wid & 3;         // k-slice 0..3 (k8 each)
    const int tok0 = blockIdx.x * BM;

    // stager geometry: thread -> (arow = tid>>2 in 0..63, as = tid&3 in 0..3)
    const int arow = tid >> 2;
    const int as   = tid & 3;

    float4* A4p[2] = { (float4*)smem, (float4*)(smem + STAGE_B) };
    float4* B4p[2] = { (float4*)(smem + A4_BYTES), (float4*)(smem + STAGE_B + A4_BYTES) };

    // consumer constant offsets (float4 units)
    const int aoff = (tgp * 32 + g) * ROW4 + ks * 4 + tg;
    const int boff = g * ROW4 + ks * 4 + tg;

    float acc[2][8][4];
#pragma unroll
    for (int mf = 0; mf < 2; mf++)
#pragma unroll
        for (int nt = 0; nt < 8; nt++)
#pragma unroll
            for (int i = 0; i < 4; i++) acc[mf][nt][i] = 0.0f;

    const float* Xp = X + (size_t)(tok0 + arow) * DIM + as * 8;
    const float* Wp = W + (size_t)arow * DIM + as * 8;

    float4 xa0, xa1, xw0, xw1;

    // ---- prolog: load + stage chunk 0 ----
    xa0 = *(const float4*)Xp;       xa1 = *(const float4*)(Xp + 4);
    xw0 = *(const float4*)Wp;       xw1 = *(const float4*)(Wp + 4);
    stage_pack(A4p[0], arow, as, xa0, xa1);
    stage_pack(B4p[0], arow, as, xw0, xw1);
    if (tid < NEXP) cnt[tid] = 0u;
    __syncthreads();

    for (int kt = 0; kt < NCHUNK; kt++) {
        const int stage = kt & 1;

        // ---- prefetch next chunk ----
        if (kt + 1 < NCHUNK) {
            Xp += BK; Wp += BK;
            xa0 = *(const float4*)Xp;   xa1 = *(const float4*)(Xp + 4);
            xw0 = *(const float4*)Wp;   xw1 = *(const float4*)(Wp + 4);
        }

        // ---- compute this warp's m32 x n64 x k8 slice ----
        {
            const float4* A4 = A4p[stage];
            const float4* B4 = B4p[stage];
            // A fragments: rows g', g'+8 (mf0) and +16, +24 (mf1)
            float4 ar0 = A4[aoff];
            float4 ar1 = A4[aoff + 8  * ROW4];
            float4 ar2 = A4[aoff + 16 * ROW4];
            float4 ar3 = A4[aoff + 24 * ROW4];
#pragma unroll
            for (int ntp = 0; ntp < 4; ntp++) {
                float4 b0 = B4[boff + (2 * ntp)     * 8 * ROW4];
                float4 b1 = B4[boff + (2 * ntp + 1) * 8 * ROW4];
                float* c00 = acc[0][2 * ntp];
                float* c10 = acc[1][2 * ntp];
                float* c01 = acc[0][2 * ntp + 1];
                float* c11 = acc[1][2 * ntp + 1];
                // term 0: hi*hi
                mma_tf32(c00, ar0.x, ar1.x, ar0.z, ar1.z, b0.x, b0.z);
                mma_tf32(c10, ar2.x, ar3.x, ar2.z, ar3.z, b0.x, b0.z);
                mma_tf32(c01, ar0.x, ar1.x, ar0.z, ar1.z, b1.x, b1.z);
                mma_tf32(c11, ar2.x, ar3.x, ar2.z, ar3.z, b1.x, b1.z);
                // term 1: hi*lo
                mma_tf32(c00, ar0.x, ar1.x, ar0.z, ar1.z, b0.y, b0.w);
                mma_tf32(c10, ar2.x, ar3.x, ar2.z, ar3.z, b0.y, b0.w);
                mma_tf32(c01, ar0.x, ar1.x, ar0.z, ar1.z, b1.y, b1.w);
                mma_tf32(c11, ar2.x, ar3.x, ar2.z, ar3.z, b1.y, b1.w);
                // term 2: lo*hi
                mma_tf32(c00, ar0.y, ar1.y, ar0.w, ar1.w, b0.x, b0.z);
                mma_tf32(c10, ar2.y, ar3.y, ar2.w, ar3.w, b0.x, b0.z);
                mma_tf32(c01, ar0.y, ar1.y, ar0.w, ar1.w, b1.x, b1.z);
                mma_tf32(c11, ar2.y, ar3.y, ar2.w, ar3.w, b1.x, b1.z);
                // term 3: lo*lo
                mma_tf32(c00, ar0.y, ar1.y, ar0.w, ar1.w, b0.y, b0.w);
                mma_tf32(c10, ar2.y, ar3.y, ar2.w, ar3.w, b0.y, b0.w);
                mma_tf32(c01, ar0.y, ar1.y, ar0.w, ar1.w, b1.y, b1.w);
                mma_tf32(c11, ar2.y, ar3.y, ar2.w, ar3.w, b1.y, b1.w);
            }
        }

        // ---- stage prefetched regs into other buffer ----
        if (kt + 1 < NCHUNK) {
            stage_pack(A4p[stage ^ 1], arow, as, xa0, xa1);
            stage_pack(B4p[stage ^ 1], arow, as, xw0, xw1);
        }
        __syncthreads();
    }

    // ---- cross-slice reduction: red[4][64][68] ----
    float* red = (float*)smem;
#pragma unroll
    for (int mf = 0; mf < 2; mf++) {
        const int row = tgp * 32 + mf * 16 + g;
#pragma unroll
        for (int nt = 0; nt < 8; nt++) {
            const int e = nt * 8 + 2 * tg;
            *(float2*)&red[((ks * BM) + row) * 68 + e] =
                make_float2(acc[mf][nt][0], acc[mf][nt][1]);
            *(float2*)&red[((ks * BM) + row + 8) * 68 + e] =
                make_float2(acc[mf][nt][2], acc[mf][nt][3]);
        }
    }
    __syncthreads();

    for (int i = tid; i < BM * NEXP; i += NTHREADS) {
        const int t = i >> 6, e = i & 63;
        float s = red[t * 68 + e]
                + red[(BM * 68) + t * 68 + e]
                + red[2 * (BM * 68) + t * 68 + e]
                + red[3 * (BM * 68) + t * 68 + e];
        red[t * 68 + e] = s;
    }
    __syncthreads();

    float* sc = red;   // [64][68]

    // ---- per-token softmax + top-2 ----
    if (tid < BM) {
        float v[64];
#pragma unroll
        for (int e = 0; e < NEXP; e++) v[e] = sc[tid * 68 + e];
        float mx = v[0];
#pragma unroll
        for (int e = 1; e < NEXP; e++) mx = fmaxf(mx, v[e]);
        float sum = 0.0f;
#pragma unroll
        for (int e = 0; e < NEXP; e++) { v[e] = expf(v[e] - mx); sum += v[e]; }
        float inv = 1.0f / sum;

        float v1 = -1.0f, v2 = -1.0f;
        int i1 = 0, i2 = 0;
#pragma unroll
        for (int e = 0; e < NEXP; e++) {
            float p = v[e] * inv;
            sc[tid * 68 + e] = p;
            if (p > v1) { v2 = v1; i2 = i1; v1 = p; i1 = e; }
            else if (p > v2) { v2 = p; i2 = e; }
        }
        float tot = v1 + v2 + 1e-20f;
        const int gt = tok0 + tid;
        out[2 * gt + 0] = (float)i1;
        out[2 * gt + 1] = (float)i2;
        out[2 * T_TOK + 2 * gt + 0] = v1 / tot;
        out[2 * T_TOK + 2 * gt + 1] = v2 / tot;

        atomicAdd(&cnt[i1], 1u);
        atomicAdd(&cnt[i2], 1u);
    }
    __syncthreads();

    // ---- per-expert sums -> global ----
    if (tid < NEXP) {
        float cs = 0.0f;
#pragma unroll 8
        for (int t = 0; t < BM; t++) cs += sc[t * 68 + tid];
        const int b = tok0 / SEQ;
        atomicAdd(&g_score_sum[b * NEXP + tid], cs);
        atomicAdd(&g_counts[b * NEXP + tid], cnt[tid]);
    }

    // ---- last-block finalize (aux loss) ----
    __threadfence();
    __syncthreads();
    if (tid == 0) {
        unsigned int v = atomicAdd(&g_done, 1u);
        last_flag = (v == (unsigned int)(GRID - 1));
    }
    __syncthreads();
    if (last_flag) {
        float* redf = (float*)smem;   // 256 floats
        const int i = tid;            // 256 = NB*NEXP
        float sv = *((volatile float*)&g_score_sum[i]);
        unsigned int cv = *((volatile unsigned int*)&g_counts[i]);
        float v = (float)cv * ((float)NEXP / (float)(SEQ * 2)) * (sv / (float)SEQ);
        g_score_sum[i] = 0.0f;
        g_counts[i] = 0u;
        if (tid == 0) g_done = 0u;
        redf[i] = v;
        __syncthreads();
        for (int s = (NB * NEXP) / 2; s > 0; s >>= 1) {
            if (i < s) redf[i] += redf[i + s];
            __syncthreads();
        }
        if (i == 0) out[4 * T_TOK] = redf[0] * (0.1f / (float)NB);
    }
}

extern "C" void kernel_launch(void* const* d_in, const int* in_sizes, int n_in,
                              void* d_out, int out_size) {
    const float* X = (const float*)d_in[0];   // [4,4096,2048] f32
    const float* W = (const float*)d_in[1];   // [64,2048] f32
    float* out = (float*)d_out;

    cudaFuncSetAttribute(moe_gate_mma, cudaFuncAttributeMaxDynamicSharedMemorySize, SMEM_BYTES);
    moe_gate_mma<<<GRID, NTHREADS, SMEM_BYTES>>>(X, W, out);
}